// round 12
// baseline (speedup 1.0000x reference)
#include <cuda_runtime.h>
#include <math.h>

#define Nx   256
#define BN   2048      // 8*256

// ---------------- scratch ----------------
__device__ float g_A [BN*128];   // h @ Wm1[0:128]
__device__ float g_Bm[BN*128];   // h @ Wm1[128:256]
__device__ float g_as[BN];
__device__ float g_bs[BN];
__device__ float g_S [BN*128];   // sum_j w_ij * relu(pre_ij)
__device__ float g_c [BN];       // sum_j w_ij
__device__ float g_M [128*128];  // Wm2 @ Wu_bot
__device__ float g_vb[128];      // bm2 @ Wu_bot + bu

typedef unsigned long long u64;

__device__ __forceinline__ u64 dup2(float a) {
    u64 r; unsigned au = __float_as_uint(a);
    asm("mov.b64 %0, {%1, %1};" : "=l"(r) : "r"(au));
    return r;
}
__device__ __forceinline__ void fma2a(u64& acc, u64 a, u64 b) {
    asm("fma.rn.f32x2 %0, %1, %2, %0;" : "+l"(acc) : "l"(a), "l"(b));
}
__device__ __forceinline__ float2 unpk(u64 v) {
    unsigned lo, hi;
    asm("mov.b64 {%0, %1}, %2;" : "=r"(lo), "=r"(hi) : "l"(v));
    return make_float2(__uint_as_float(lo), __uint_as_float(hi));
}

// =======================================================================
// Stage 1: grid 273, block 256, dyn smem 53248 (-> 2+ blocks/SM, 1 wave)
//  bid 0..255  : 32x64 tiles of h @ [Wm1t|Wm1b]   (mt 0..63, nt 0..3)
//  bid 256..263: 32x64 tiles of Wm2 @ Wu_bot -> g_M
//  bid 264..271: attention dots (256 rows each)
//  bid 272     : vb
//  warp micro: 8 rows x 32 cols, row-pair f32x2 packing:
//    per k: 2 bcast LDS.128 (A rows) + 1 LDS.32 (W) + dup + 4 fma2
// =======================================================================
#define S1_SMEM ((128*36 + 128*68) * 4)

__global__ void __launch_bounds__(256) k_stage1(
    const float* __restrict__ h,   const float* __restrict__ Wm1,
    const float* __restrict__ Wa,  const float* __restrict__ Wm2,
    const float* __restrict__ bm2, const float* __restrict__ Wu,
    const float* __restrict__ bu)
{
    extern __shared__ float sm[];
    const int bid = blockIdx.x;
    const int t   = threadIdx.x;
    const int wrp = t >> 5, lane = t & 31;

    if (bid < 264) {
        float* At = sm;              // [128][36]  k-major transposed A (32 rows)
        float* Ws = sm + 128*36;     // [128][68]  k-major W (64 cols)
        const float *A, *W;
        float* dst;
        if (bid < 256) {
            int mt = bid >> 2, nt = bid & 3;
            int p = nt >> 1, col0 = (nt & 1) * 64;
            A   = h + mt*32*128;
            W   = ((p == 0) ? Wm1 : (Wm1 + 128*128)) + col0;
            dst = ((p == 0) ? g_A : g_Bm) + mt*32*128 + col0;
        } else {
            int bb = bid - 256;
            int mm = bb >> 1, col0 = (bb & 1) * 64;
            A   = Wm2 + mm*32*128;
            W   = Wu + 128*128 + col0;
            dst = g_M + mm*32*128 + col0;
        }
        // ---- A tile 32x128 -> transposed (lane = row: conflict-free STS)
#pragma unroll
        for (int n = 0; n < 4; n++) {
            int idx = t + n*256;              // 0..1023
            int r   = idx & 31;
            int kq  = (idx >> 5) * 4;
            float4 v = *(const float4*)&A[r*128 + kq];
            At[(kq+0)*36 + r] = v.x;
            At[(kq+1)*36 + r] = v.y;
            At[(kq+2)*36 + r] = v.z;
            At[(kq+3)*36 + r] = v.w;
        }
        // ---- W tile 128x64
#pragma unroll
        for (int n = 0; n < 8; n++) {
            int idx = t + n*256;
            int wk = idx >> 4, wn = (idx & 15) * 4;
            *(float4*)&Ws[wk*68 + wn] = *(const float4*)&W[wk*128 + wn];
        }
        __syncthreads();

        // ---- warp: rows rg*8..+7, cols cg*32 + lane
        const int rg = wrp >> 1, cg = wrp & 1;
        const int c  = cg*32 + lane;
        const float* wp = Ws + c;
        const int abase = rg*8;

        u64 acc0 = 0ull, acc1 = 0ull, acc2 = 0ull, acc3 = 0ull;
#pragma unroll 4
        for (int k = 0; k < 128; k++) {
            ulonglong2 a01 = *(const ulonglong2*)&At[k*36 + abase];     // rows 0..3
            ulonglong2 a23 = *(const ulonglong2*)&At[k*36 + abase + 4]; // rows 4..7
            u64 w2 = dup2(wp[k*68]);
            fma2a(acc0, a01.x, w2);
            fma2a(acc1, a01.y, w2);
            fma2a(acc2, a23.x, w2);
            fma2a(acc3, a23.y, w2);
        }
        {
            float2 p;
            p = unpk(acc0);
            dst[(abase+0)*128 + c] = p.x; dst[(abase+1)*128 + c] = p.y;
            p = unpk(acc1);
            dst[(abase+2)*128 + c] = p.x; dst[(abase+3)*128 + c] = p.y;
            p = unpk(acc2);
            dst[(abase+4)*128 + c] = p.x; dst[(abase+5)*128 + c] = p.y;
            p = unpk(acc3);
            dst[(abase+6)*128 + c] = p.x; dst[(abase+7)*128 + c] = p.y;
        }

    } else if (bid < 272) {
        // ---- dots: 256 rows per block, 32 rows per warp
        const int rowbase = (bid - 264) * 256 + wrp * 32;
        float4 wa1 = *(const float4*)&Wa[lane*4];
        float4 wa2 = *(const float4*)&Wa[128 + lane*4];
#pragma unroll 4
        for (int rr = 0; rr < 32; rr++) {
            int row = rowbase + rr;
            float4 hv = *(const float4*)&h[row*128 + lane*4];
            float sa = hv.x*wa1.x + hv.y*wa1.y + hv.z*wa1.z + hv.w*wa1.w;
            float sb = hv.x*wa2.x + hv.y*wa2.y + hv.z*wa2.z + hv.w*wa2.w;
#pragma unroll
            for (int o = 16; o; o >>= 1) {
                sa += __shfl_xor_sync(0xffffffffu, sa, o);
                sb += __shfl_xor_sync(0xffffffffu, sb, o);
            }
            if (lane == 0) { g_as[row] = sa; g_bs[row] = sb; }
        }
    } else {
        if (t < 128) {
            float acc = bu[t];
#pragma unroll 16
            for (int k = 0; k < 128; k++)
                acc = fmaf(bm2[k], Wu[(128 + k)*128 + t], acc);
            g_vb[t] = acc;
        }
    }
}

// =======================================================================
// k_pair (R2-proven, verbatim): grid (16,8), block 512, dyn smem 202752
// =======================================================================
#define PAIR_SMEM ((32768 + 16384 + 2048 + 256) * 4)

__global__ void __launch_bounds__(512, 1) k_pair(
    const float* __restrict__ dist, const int* __restrict__ adj,
    const float* __restrict__ Wm1,  const float* __restrict__ bm1,
    const float* __restrict__ Wa,   const float* __restrict__ ba)
{
    extern __shared__ float sm[];
    float*  Bsh  = sm;                       // 256*128
    float4* dwsh = (float4*)(sm + 32768);    // [16][256] {d,d,w,w}
    float*  Ash  = sm + 32768 + 16384;       // 16*128 (A + bm1)
    float*  bssh = Ash + 2048;               // 256

    const int t = threadIdx.x;
    const int b = blockIdx.y, i0 = blockIdx.x * 16;
    const int lane = t & 31, wrp = t >> 5;

    // ---- fills
    {
        const float4* src = (const float4*)(g_Bm + (size_t)b*Nx*128);
        float4* d4 = (float4*)Bsh;
#pragma unroll
        for (int k = 0; k < 16; k++) d4[t + k*512] = src[t + k*512];
    }
#pragma unroll
    for (int k = 0; k < 4; k++) {
        int idx = t + k*512;
        Ash[idx] = g_A[(size_t)(b*Nx + i0)*128 + idx] + bm1[idx & 127];
    }
    if (t < 256) bssh[t] = g_bs[b*Nx + t];
    __syncthreads();

    // ---- phase 1: warp wrp handles i = i0 + wrp
    const float wa_d = Wa[256];
    {
        const int ig = b*Nx + i0 + wrp;
        const float a_i = g_as[ig] + ba[0];
        float l[8], dv[8]; int mk[8];
#pragma unroll
        for (int jj = 0; jj < 8; jj++) {
            int j = jj*32 + lane;
            float d = dist[(size_t)ig*Nx + j];
            int   m = adj [(size_t)ig*Nx + j];
            float x = fmaf(d, wa_d, a_i + bssh[j]);
            x = (x >= 0.f) ? x : 0.2f * x;
            l[jj] = m ? x : -1e9f;
            dv[jj] = d; mk[jj] = m;
        }
        float mx = l[0];
#pragma unroll
        for (int jj = 1; jj < 8; jj++) mx = fmaxf(mx, l[jj]);
#pragma unroll
        for (int o = 16; o; o >>= 1) mx = fmaxf(mx, __shfl_xor_sync(0xffffffffu, mx, o));
        float sum = 0.f, cs = 0.f;
#pragma unroll
        for (int jj = 0; jj < 8; jj++) {
            float e = expf(l[jj] - mx);
            l[jj] = e;
            sum += e;
            cs  += mk[jj] ? e : 0.f;
        }
#pragma unroll
        for (int o = 16; o; o >>= 1) {
            sum += __shfl_xor_sync(0xffffffffu, sum, o);
            cs  += __shfl_xor_sync(0xffffffffu, cs,  o);
        }
        float inv = 1.f / sum;
#pragma unroll
        for (int jj = 0; jj < 8; jj++) {
            int j = jj*32 + lane;
            float w = mk[jj] ? l[jj]*inv : 0.f;
            dwsh[wrp*256 + j] = make_float4(dv[jj], dv[jj], w, w);
        }
        if (lane == 0) g_c[ig] = cs * inv;
    }

    // ---- per-thread registers for phase 2
    const int cp = t & 63, q = t >> 6;
    u64 a2[16], acc2[16];
#pragma unroll
    for (int i = 0; i < 16; i++) {
        a2[i]   = *(const u64*)&Ash[i*128 + cp*2];
        acc2[i] = 0ull;
    }
    const u64 wd2 = *(const u64*)&Wm1[256*128 + cp*2];
    __syncthreads();

    // ---- phase 2
    const ulonglong2* dw2 = (const ulonglong2*)dwsh;
#pragma unroll 1
    for (int jj = 0; jj < 32; jj++) {
        int j = jj*8 + q;
        u64 b2 = *(const u64*)&Bsh[j*128 + cp*2];
        const ulonglong2* p = dw2 + j;
#pragma unroll
        for (int i = 0; i < 16; i++) {
            ulonglong2 dw = p[i*256];
            asm("{\n\t"
                ".reg .b64 tt;\n\t"
                ".reg .f32 lo, hi;\n\t"
                "add.rn.f32x2 tt, %1, %2;\n\t"
                "fma.rn.f32x2 tt, %3, %4, tt;\n\t"
                "mov.b64 {lo, hi}, tt;\n\t"
                "max.f32 lo, lo, 0f00000000;\n\t"
                "max.f32 hi, hi, 0f00000000;\n\t"
                "mov.b64 tt, {lo, hi};\n\t"
                "fma.rn.f32x2 %0, %5, tt, %0;\n\t"
                "}"
                : "+l"(acc2[i])
                : "l"(a2[i]), "l"(b2), "l"(dw.x), "l"(wd2), "l"(dw.y));
        }
    }
    __syncthreads();

    // ---- reduce over q (8 partials), reuse dwsh region
    u64* part = (u64*)dwsh;
#pragma unroll
    for (int i = 0; i < 16; i++) part[(i*8 + q)*64 + cp] = acc2[i];
    __syncthreads();
#pragma unroll
    for (int rep = 0; rep < 2; rep++) {
        int it = t + rep*512;
        int i = it >> 6, cpp = it & 63;
        float2 s = make_float2(0.f, 0.f);
#pragma unroll
        for (int qq = 0; qq < 8; qq++) {
            float2 v = unpk(part[(i*8 + qq)*64 + cpp]);
            s.x += v.x; s.y += v.y;
        }
        *(float2*)&g_S[(size_t)(b*Nx + i0 + i)*128 + cpp*2] = s;
    }
}

// =======================================================================
// k_out (R2-proven, verbatim): out = relu( [h|S] @ [Wu_top;M] + c*vb )
// grid (64,2), block 256
// =======================================================================
__global__ void __launch_bounds__(256) k_out(
    const float* __restrict__ h, const float* __restrict__ Wu,
    float* __restrict__ out)
{
    __shared__ float As[32][36];
    __shared__ float Ws[32][68];
    const int t = threadIdx.x;
    const int row0 = blockIdx.x * 32, col0 = blockIdx.y * 64;
    const int ty = t >> 4, tx = t & 15;
    float acc[2][4];
#pragma unroll
    for (int r = 0; r < 2; r++)
#pragma unroll
        for (int c = 0; c < 4; c++) acc[r][c] = 0.f;

    for (int k0 = 0; k0 < 256; k0 += 32) {
        {
            int r  = t >> 3;
            int kq = (t & 7) * 4;
            int kg = k0 + kq;
            const float* src = (kg < 128) ? &h  [(row0 + r)*128 + kg]
                                          : &g_S[(row0 + r)*128 + kg - 128];
            float4 v = *(const float4*)src;
            As[kq+0][r] = v.x; As[kq+1][r] = v.y;
            As[kq+2][r] = v.z; As[kq+3][r] = v.w;
        }
#pragma unroll
        for (int n = 0; n < 2; n++) {
            int l  = t + n*256;
            int wk = l >> 4;
            int wn = (l & 15) * 4;
            int kg = k0 + wk;
            const float* src = (kg < 128) ? &Wu [kg*128 + col0 + wn]
                                          : &g_M[(kg - 128)*128 + col0 + wn];
            *(float4*)&Ws[wk][wn] = *(const float4*)src;
        }
        __syncthreads();
#pragma unroll
        for (int kk = 0; kk < 32; kk++) {
            float2 a2 = *(const float2*)&As[kk][ty*2];
            float4 b4 = *(const float4*)&Ws[kk][tx*4];
            acc[0][0] = fmaf(a2.x, b4.x, acc[0][0]);
            acc[0][1] = fmaf(a2.x, b4.y, acc[0][1]);
            acc[0][2] = fmaf(a2.x, b4.z, acc[0][2]);
            acc[0][3] = fmaf(a2.x, b4.w, acc[0][3]);
            acc[1][0] = fmaf(a2.y, b4.x, acc[1][0]);
            acc[1][1] = fmaf(a2.y, b4.y, acc[1][1]);
            acc[1][2] = fmaf(a2.y, b4.z, acc[1][2]);
            acc[1][3] = fmaf(a2.y, b4.w, acc[1][3]);
        }
        __syncthreads();
    }

    float4 vb4 = *(const float4*)&g_vb[col0 + tx*4];
#pragma unroll
    for (int r = 0; r < 2; r++) {
        int row = row0 + ty*2 + r;
        float cr = g_c[row];
        float4 v;
        v.x = fmaxf(fmaf(cr, vb4.x, acc[r][0]), 0.f);
        v.y = fmaxf(fmaf(cr, vb4.y, acc[r][1]), 0.f);
        v.z = fmaxf(fmaf(cr, vb4.z, acc[r][2]), 0.f);
        v.w = fmaxf(fmaf(cr, vb4.w, acc[r][3]), 0.f);
        *(float4*)&out[row*128 + col0 + tx*4] = v;
    }
}

// =======================================================================
extern "C" void kernel_launch(void* const* d_in, const int* in_sizes, int n_in,
                              void* d_out, int out_size)
{
    const float* h    = (const float*)d_in[0];
    const int*   adj  = (const int*)  d_in[1];
    const float* dist = (const float*)d_in[2];
    const float* Wm1  = (const float*)d_in[3];
    const float* bm1  = (const float*)d_in[4];
    const float* Wm2  = (const float*)d_in[5];
    const float* bm2  = (const float*)d_in[6];
    const float* Wa   = (const float*)d_in[7];
    const float* ba   = (const float*)d_in[8];
    const float* Wu   = (const float*)d_in[9];
    const float* bu   = (const float*)d_in[10];
    float* out = (float*)d_out;

    cudaFuncSetAttribute(k_stage1, cudaFuncAttributeMaxDynamicSharedMemorySize,
                         S1_SMEM);
    cudaFuncSetAttribute(k_pair, cudaFuncAttributeMaxDynamicSharedMemorySize,
                         PAIR_SMEM);

    k_stage1<<<273, 256, S1_SMEM>>>(h, Wm1, Wa, Wm2, bm2, Wu, bu);
    k_pair  <<<dim3(16, 8), 512, PAIR_SMEM>>>(dist, adj, Wm1, bm1, Wa, ba);
    k_out   <<<dim3(64, 2), 256>>>(h, Wu, out);
}